// round 16
// baseline (speedup 1.0000x reference)
#include <cuda_runtime.h>
#include <cuda_bf16.h>
#include <math.h>
#include <stdint.h>

#define Bb 4
#define Ll 1024
#define Ee 1024
#define Hh 16
#define DHh 64
#define TOPKk 32

// -------- scratch (no allocs allowed) --------
__device__ float g_q [Bb*Ll*Ee];
__device__ float g_k [Bb*Ll*Ee];
__device__ float g_v [Bb*Ll*Ee];

// split planes
__device__ __nv_bfloat16 g_vs1[Bb*Ll*Ee];   // V split, then attn-out split
__device__ __nv_bfloat16 g_vs2[Bb*Ll*Ee];
__device__ __nv_bfloat16 g_wv1[Ee*Ee];
__device__ __nv_bfloat16 g_wv2[Ee*Ee];
__device__ __nv_bfloat16 g_wo1[Ee*Ee];
__device__ __nv_bfloat16 g_wo2[Ee*Ee];

__device__ __forceinline__ uint32_t smem_u32(const void* p) {
    uint32_t a;
    asm("{ .reg .u64 t; cvta.to.shared.u64 t, %1; cvt.u32.u64 %0, t; }" : "=r"(a) : "l"(p));
    return a;
}
__device__ __forceinline__ void cp_async4(uint32_t saddr, const void* g) {
    asm volatile("cp.async.ca.shared.global [%0], [%1], 4;" :: "r"(saddr), "l"(g));
}
__device__ __forceinline__ void cp_async16(uint32_t saddr, const void* g) {
    asm volatile("cp.async.cg.shared.global [%0], [%1], 16;" :: "r"(saddr), "l"(g));
}
#define CP_COMMIT() asm volatile("cp.async.commit_group;" ::: "memory")
#define CP_WAIT(n)  asm volatile("cp.async.wait_group %0;" :: "n"(n) : "memory")

// ============================================================
// Scalar fp32 GEMM — round-1 fma chain (bit-identical values &
// order), cp.async double-buffered loads (schedule-only change).
// ============================================================
#define GBM 128
#define GBN 128
#define GBK 16

__global__ __launch_bounds__(256) void gemm_nt_bias(
    const float* __restrict__ X, const float* __restrict__ W,
    const float* __restrict__ bias, float* __restrict__ out,
    int M, int N, int K)
{
    __shared__ float As[2][GBK][GBM];
    __shared__ float Bs[2][GBK][GBN];

    const int tid = threadIdx.x;
    const int bm = blockIdx.y * GBM;
    const int bn = blockIdx.x * GBN;

    const int tr = (tid / 16) * 8;
    const int tc = (tid % 16) * 8;

    const int arow  = tid >> 2;     // 0..63
    const int acol4 = tid & 3;      // k-group of 4

    const uint32_t sA0 = smem_u32(&As[0][0][0]);
    const uint32_t sB0 = smem_u32(&Bs[0][0][0]);
    const uint32_t bufB = (uint32_t)(GBK * GBM * sizeof(float));  // 8192

    float acc[8][8] = {};

    const int NCH = K / GBK;

    // issue chunk 0 into buffer 0
    #pragma unroll
    for (int r = 0; r < 2; r++) {
        int row = arow + r * 64;
        const float* gx = X + (size_t)(bm + row) * K + acol4 * 4;
        const float* gw = W + (size_t)(bn + row) * K + acol4 * 4;
        #pragma unroll
        for (int j = 0; j < 4; j++) {
            // As[0][acol4*4+j][row], Bs[0][...][row]
            uint32_t off = (uint32_t)((acol4 * 4 + j) * GBM + row) * 4;
            cp_async4(sA0 + off, gx + j);
            cp_async4(sB0 + off, gw + j);
        }
    }
    CP_COMMIT();

    for (int kc = 0; kc < NCH; kc++) {
        // issue chunk kc+1 into the other buffer
        if (kc + 1 < NCH) {
            const int k0 = (kc + 1) * GBK;
            const uint32_t stage = (uint32_t)((kc + 1) & 1) * bufB;
            #pragma unroll
            for (int r = 0; r < 2; r++) {
                int row = arow + r * 64;
                const float* gx = X + (size_t)(bm + row) * K + k0 + acol4 * 4;
                const float* gw = W + (size_t)(bn + row) * K + k0 + acol4 * 4;
                #pragma unroll
                for (int j = 0; j < 4; j++) {
                    uint32_t off = stage + (uint32_t)((acol4 * 4 + j) * GBM + row) * 4;
                    cp_async4(sA0 + off, gx + j);
                    cp_async4(sB0 + off, gw + j);
                }
            }
            CP_COMMIT();
            CP_WAIT(1);   // chunk kc ready
        } else {
            CP_WAIT(0);
        }
        __syncthreads();

        const int cur = kc & 1;
        #pragma unroll
        for (int k = 0; k < GBK; k++) {
            float ra[8], rb[8];
            #pragma unroll
            for (int i = 0; i < 8; i++) ra[i] = As[cur][k][tr + i];
            #pragma unroll
            for (int j = 0; j < 8; j++) rb[j] = Bs[cur][k][tc + j];
            #pragma unroll
            for (int i = 0; i < 8; i++)
                #pragma unroll
                for (int j = 0; j < 8; j++)
                    acc[i][j] = fmaf(ra[i], rb[j], acc[i][j]);
        }
        __syncthreads();
    }

    #pragma unroll
    for (int i = 0; i < 8; i++) {
        #pragma unroll
        for (int j = 0; j < 8; j++) {
            out[(size_t)(bm + tr + i) * N + bn + tc + j] = acc[i][j] + bias[bn + tc + j];
        }
    }
}

// ============================================================
// bf16x2 split
// ============================================================
__global__ void split2_kernel(const float* __restrict__ src,
                              __nv_bfloat16* __restrict__ p1,
                              __nv_bfloat16* __restrict__ p2, int n)
{
    int i = blockIdx.x * blockDim.x + threadIdx.x;
    if (i >= n) return;
    float x = src[i];
    __nv_bfloat16 b1 = __float2bfloat16_rn(x);
    float r1 = x - __bfloat162float(b1);
    p1[i] = b1;
    p2[i] = __float2bfloat16_rn(r1);
}

// ============================================================
// mma helpers
// ============================================================
__device__ __forceinline__ void mma16816(
    float& d0, float& d1, float& d2, float& d3,
    uint32_t a0, uint32_t a1, uint32_t a2, uint32_t a3,
    uint32_t b0, uint32_t b1)
{
    asm volatile(
        "mma.sync.aligned.m16n8k16.row.col.f32.bf16.bf16.f32 "
        "{%0,%1,%2,%3}, {%4,%5,%6,%7}, {%8,%9}, {%0,%1,%2,%3};"
        : "+f"(d0), "+f"(d1), "+f"(d2), "+f"(d3)
        : "r"(a0), "r"(a1), "r"(a2), "r"(a3), "r"(b0), "r"(b1));
}
__device__ __forceinline__ void ldsm_x4(uint32_t& r0, uint32_t& r1,
                                        uint32_t& r2, uint32_t& r3, uint32_t saddr)
{
    asm volatile("ldmatrix.sync.aligned.m8n8.x4.shared.b16 {%0,%1,%2,%3}, [%4];"
        : "=r"(r0), "=r"(r1), "=r"(r2), "=r"(r3) : "r"(saddr));
}

#define TK 1024
#define TN 1024
#define NCHUNK (TK / 32)
#define SROWB 80
#define TILE_B (128 * SROWB)
#define STAGE_B (4 * TILE_B)
#define TG_SMEM (2 * STAGE_B)

// ============================================================
// 3-term bf16x2 GEMM (v / out projections) — round-7 version
// ============================================================
__global__ __launch_bounds__(256, 2) void gemm_bf16x2_mma(
    const __nv_bfloat16* __restrict__ A1, const __nv_bfloat16* __restrict__ A2,
    const __nv_bfloat16* __restrict__ B1, const __nv_bfloat16* __restrict__ B2,
    const float* __restrict__ bias, float* __restrict__ out)
{
    extern __shared__ char smem[];
    const uint32_t smem_b = smem_u32(smem);

    const int tid = threadIdx.x;
    const int wid = tid >> 5;
    const int lane = tid & 31;
    const int g  = lane >> 2;
    const int tg = lane & 3;

    const int bm = blockIdx.y * 128;
    const int bn = blockIdx.x * 128;
    const int wm = (wid >> 1) * 32;
    const int wn = (wid & 1) * 64;

    const uint32_t lrow = (uint32_t)(lane & 15);
    const uint32_t lcol = (uint32_t)((lane >> 4) << 3);

    const __nv_bfloat16* gp[4] = {A1, A2, B1, B2};
    const int gbase[4] = {bm, bm, bn, bn};

    float acc[2][8][4] = {};

    for (int kc = 0; kc < NCHUNK + 1; kc++) {
        if (kc < NCHUNK) {
            const int k0 = kc * 32;
            const uint32_t stage_off = (uint32_t)(kc & 1) * STAGE_B;
            #pragma unroll
            for (int it = 0; it < 8; it++) {
                int c = tid + it * 256;
                int t = c >> 9;
                int rem = c & 511;
                int row = rem >> 2;
                int seg = rem & 3;
                uint32_t sa = smem_b + stage_off + (uint32_t)t * TILE_B
                            + (uint32_t)row * SROWB + (uint32_t)seg * 16;
                const __nv_bfloat16* gsrc = gp[t] + (size_t)(gbase[t] + row) * TK + k0 + seg * 8;
                cp_async16(sa, gsrc);
            }
            CP_COMMIT();
        }
        if (kc == 0) continue;

        if (kc < NCHUNK) { CP_WAIT(1); } else { CP_WAIT(0); }
        __syncthreads();

        const uint32_t st_u = smem_b + (uint32_t)((kc - 1) & 1) * STAGE_B;

        #pragma unroll
        for (int ks = 0; ks < 2; ks++) {
            const uint32_t coff = (uint32_t)(ks * 16) * 2 + lcol * 2;

            uint32_t af[2][2][4];
            #pragma unroll
            for (int p = 0; p < 2; p++)
                #pragma unroll
                for (int mt = 0; mt < 2; mt++) {
                    uint32_t addr = st_u + (uint32_t)p * TILE_B
                                  + ((uint32_t)(wm + mt * 16) + lrow) * SROWB + coff;
                    ldsm_x4(af[p][mt][0], af[p][mt][1], af[p][mt][2], af[p][mt][3], addr);
                }
            #pragma unroll
            for (int np = 0; np < 4; np++) {
                uint32_t bf[2][2][2];
                #pragma unroll
                for (int p = 0; p < 2; p++) {
                    uint32_t addr = st_u + (uint32_t)(2 + p) * TILE_B
                                  + ((uint32_t)(wn + np * 16) + lrow) * SROWB + coff;
                    ldsm_x4(bf[p][0][0], bf[p][1][0], bf[p][0][1], bf[p][1][1], addr);
                }
                #pragma unroll
                for (int ntl = 0; ntl < 2; ntl++) {
                    const int nt = np * 2 + ntl;
                    #pragma unroll
                    for (int mt = 0; mt < 2; mt++) {
                        mma16816(acc[mt][nt][0], acc[mt][nt][1], acc[mt][nt][2], acc[mt][nt][3],
                                 af[0][mt][0], af[0][mt][1], af[0][mt][2], af[0][mt][3],
                                 bf[0][ntl][0], bf[0][ntl][1]);
                        mma16816(acc[mt][nt][0], acc[mt][nt][1], acc[mt][nt][2], acc[mt][nt][3],
                                 af[0][mt][0], af[0][mt][1], af[0][mt][2], af[0][mt][3],
                                 bf[1][ntl][0], bf[1][ntl][1]);
                        mma16816(acc[mt][nt][0], acc[mt][nt][1], acc[mt][nt][2], acc[mt][nt][3],
                                 af[1][mt][0], af[1][mt][1], af[1][mt][2], af[1][mt][3],
                                 bf[0][ntl][0], bf[0][ntl][1]);
                    }
                }
            }
        }
        __syncthreads();
    }

    #pragma unroll
    for (int mt = 0; mt < 2; mt++) {
        #pragma unroll
        for (int nt = 0; nt < 8; nt++) {
            int m0 = bm + wm + mt * 16 + g;
            int n0 = bn + wn + nt * 8 + tg * 2;
            float b0 = bias[n0], b1 = bias[n0 + 1];
            float2 lo = make_float2(acc[mt][nt][0] + b0, acc[mt][nt][1] + b1);
            float2 hi = make_float2(acc[mt][nt][2] + b0, acc[mt][nt][3] + b1);
            *(float2*)(out + (size_t)m0 * TN + n0)       = lo;
            *(float2*)(out + (size_t)(m0 + 8) * TN + n0) = hi;
        }
    }
}

// ============================================================
// Attention (round-14 version — bitmask deferred-insert scan,
// fused bf16x2 split epilogue; bit-identical selection)
// ============================================================
#define ATT_QT 128
#define ATT_KT 32
#define ATT_THREADS 256

#define SM_QT   0
#define SM_KT   (SM_QT + 64*128)
#define SM_S    (SM_KT + 64*ATT_KT)
#define SM_TV   (SM_S  + 128*33)
#define SM_TI   (SM_TV + 128*33)
#define ATT_SMEM_FLOATS (SM_TI + 128*33)

__global__ __launch_bounds__(ATT_THREADS) void attn_topk_kernel(
    const float* __restrict__ gq, const float* __restrict__ gk,
    const float* __restrict__ gv,
    __nv_bfloat16* __restrict__ ao1, __nv_bfloat16* __restrict__ ao2)
{
    extern __shared__ float sm[];
    float* sQt = sm + SM_QT;
    float* sKt = sm + SM_KT;
    float* sS  = sm + SM_S;
    float* sTV = sm + SM_TV;
    int*   sTI = (int*)(sm + SM_TI);

    const int tid = threadIdx.x;
    const int bh  = blockIdx.y;
    const int b   = bh / Hh;
    const int h   = bh % Hh;
    const int l0  = blockIdx.x * ATT_QT;

    for (int idx = tid; idx < ATT_QT * DHh; idx += ATT_THREADS) {
        int qq = idx >> 6;
        int d  = idx & 63;
        sQt[d * ATT_QT + qq] = gq[((size_t)(b * Ll + l0 + qq)) * Ee + h * DHh + d];
    }

    if (tid < 128) {
        #pragma unroll
        for (int j = 0; j < TOPKk; j++) {
            sTV[tid * 33 + j] = -INFINITY;
            sTI[tid * 33 + j] = 0;
        }
    }
    float curMin = -INFINITY;
    int   curPos = 0;

    const int ty = tid >> 3;
    const int tx = tid & 7;

    for (int kt = 0; kt < Ll / ATT_KT; kt++) {
        for (int idx = tid; idx < ATT_KT * DHh; idx += ATT_THREADS) {
            int kk = idx >> 6;
            int d  = idx & 63;
            sKt[d * ATT_KT + kk] = gk[((size_t)(b * Ll + kt * ATT_KT + kk)) * Ee + h * DHh + d];
        }
        __syncthreads();

        float acc[4][4] = {};
        #pragma unroll 8
        for (int d = 0; d < DHh; d++) {
            float ra[4], rb[4];
            *(float4*)&ra[0] = *(const float4*)&sQt[d * ATT_QT + ty * 4];
            *(float4*)&rb[0] = *(const float4*)&sKt[d * ATT_KT + tx * 4];
            #pragma unroll
            for (int i = 0; i < 4; i++)
                #pragma unroll
                for (int j = 0; j < 4; j++)
                    acc[i][j] = fmaf(ra[i], rb[j], acc[i][j]);
        }
        #pragma unroll
        for (int i = 0; i < 4; i++)
            #pragma unroll
            for (int j = 0; j < 4; j++)
                sS[(ty * 4 + i) * 33 + tx * 4 + j] = acc[i][j] * 0.125f;
        __syncthreads();

        if (tid < 128) {
            unsigned int mask = 0;
            const float gateMin = curMin;
            #pragma unroll
            for (int kk = 0; kk < ATT_KT; kk++) {
                float s = sS[tid * 33 + kk];
                if (s > gateMin) mask |= (1u << kk);
            }
            while (mask) {
                const int kk = __ffs(mask) - 1;
                mask &= mask - 1;
                float s = sS[tid * 33 + kk];
                if (s > curMin) {
                    sTV[tid * 33 + curPos] = s;
                    sTI[tid * 33 + curPos] = kt * ATT_KT + kk;
                    float mn = sTV[tid * 33];
                    int   mp = 0;
                    #pragma unroll
                    for (int j = 1; j < TOPKk; j++) {
                        float v = sTV[tid * 33 + j];
                        if (v < mn) { mn = v; mp = j; }
                    }
                    curMin = mn; curPos = mp;
                }
            }
        }
        __syncthreads();
    }

    const int warp = tid >> 5;
    const int lane = tid & 31;
    for (int qi = warp; qi < ATT_QT; qi += 8) {
        float v  = sTV[qi * 33 + lane];
        int   ki = sTI[qi * 33 + lane];

        float mx = v;
        #pragma unroll
        for (int o = 16; o; o >>= 1) mx = fmaxf(mx, __shfl_xor_sync(0xffffffffu, mx, o));
        float e = expf(v - mx);
        float se = e;
        #pragma unroll
        for (int o = 16; o; o >>= 1) se += __shfl_xor_sync(0xffffffffu, se, o);
        float w = e / se;

        float a0 = 0.f, a1 = 0.f;
        #pragma unroll
        for (int j = 0; j < TOPKk; j++) {
            float wj = __shfl_sync(0xffffffffu, w, j);
            int   kj = __shfl_sync(0xffffffffu, ki, j);
            const float* vr = gv + ((size_t)(b * Ll + kj)) * Ee + h * DHh;
            a0 = fmaf(wj, vr[lane],      a0);
            a1 = fmaf(wj, vr[lane + 32], a1);
        }
        size_t base = ((size_t)(b * Ll + l0 + qi)) * Ee + h * DHh;
        __nv_bfloat16 b0 = __float2bfloat16_rn(a0);
        ao1[base + lane]      = b0;
        ao2[base + lane]      = __float2bfloat16_rn(a0 - __bfloat162float(b0));
        __nv_bfloat16 b1h = __float2bfloat16_rn(a1);
        ao1[base + lane + 32] = b1h;
        ao2[base + lane + 32] = __float2bfloat16_rn(a1 - __bfloat162float(b1h));
    }
}

// ============================================================
extern "C" void kernel_launch(void* const* d_in, const int* in_sizes, int n_in,
                              void* d_out, int out_size)
{
    const float* Q  = (const float*)d_in[0];
    const float* K_ = (const float*)d_in[1];
    const float* V  = (const float*)d_in[2];
    const float* Wq = (const float*)d_in[3];
    const float* bq = (const float*)d_in[4];
    const float* Wk = (const float*)d_in[5];
    const float* bk = (const float*)d_in[6];
    const float* Wv = (const float*)d_in[7];
    const float* bv = (const float*)d_in[8];
    const float* Wo = (const float*)d_in[9];
    const float* bo = (const float*)d_in[10];
    float* out = (float*)d_out;

    float *gq, *gk, *gv;
    cudaGetSymbolAddress((void**)&gq,  g_q);
    cudaGetSymbolAddress((void**)&gk,  g_k);
    cudaGetSymbolAddress((void**)&gv,  g_v);
    __nv_bfloat16 *vs1, *vs2, *wv1, *wv2, *wo1, *wo2;
    cudaGetSymbolAddress((void**)&vs1, g_vs1);
    cudaGetSymbolAddress((void**)&vs2, g_vs2);
    cudaGetSymbolAddress((void**)&wv1, g_wv1);
    cudaGetSymbolAddress((void**)&wv2, g_wv2);
    cudaGetSymbolAddress((void**)&wo1, g_wo1);
    cudaGetSymbolAddress((void**)&wo2, g_wo2);

    static cudaStream_t sV = nullptr;
    static cudaEvent_t eFork = nullptr, eV = nullptr;
    if (sV == nullptr) {
        cudaStreamCreateWithFlags(&sV, cudaStreamNonBlocking);
        cudaEventCreateWithFlags(&eFork, cudaEventDisableTiming);
        cudaEventCreateWithFlags(&eV, cudaEventDisableTiming);
    }

    const int M = Bb * Ll;
    const int N = Ee;
    const int K = Ee;

    dim3 gblock(256);
    dim3 ggrid(N / GBN, M / GBM);
    dim3 tgrid(N / 128, M / 128);

    cudaFuncSetAttribute(gemm_bf16x2_mma,
                         cudaFuncAttributeMaxDynamicSharedMemorySize, TG_SMEM);
    size_t attSmem = ATT_SMEM_FLOATS * sizeof(float);
    cudaFuncSetAttribute(attn_topk_kernel,
                         cudaFuncAttributeMaxDynamicSharedMemorySize, (int)attSmem);

    // ---- fork: v-path runs concurrently with q/k scalar GEMMs ----
    cudaEventRecord(eFork, 0);
    cudaStreamWaitEvent(sV, eFork, 0);

    split2_kernel<<<(M*K + 255)/256, 256, 0, sV>>>(V,  vs1, vs2, M*K);
    split2_kernel<<<(N*K + 255)/256, 256, 0, sV>>>(Wv, wv1, wv2, N*K);
    gemm_bf16x2_mma<<<tgrid, 256, TG_SMEM, sV>>>(vs1, vs2, wv1, wv2, bv, gv);
    split2_kernel<<<(N*K + 255)/256, 256, 0, sV>>>(Wo, wo1, wo2, N*K);
    cudaEventRecord(eV, sV);

    // ---- main: q, k projections (cp.async pipelined, bit-identical) ----
    gemm_nt_bias<<<ggrid, gblock>>>(Q,  Wq, bq, gq, M, N, K);
    gemm_nt_bias<<<ggrid, gblock>>>(K_, Wk, bk, gk, M, N, K);

    // ---- join: attention needs q, k (main) and v (side) ----
    cudaStreamWaitEvent(0, eV, 0);

    dim3 agrid(Ll / ATT_QT, Bb * Hh);
    attn_topk_kernel<<<agrid, ATT_THREADS, attSmem>>>(gq, gk, gv, vs1, vs2);

    // ---- output projection (3-term bf16x2), split fused into attn ----
    gemm_bf16x2_mma<<<tgrid, 256, TG_SMEM>>>(vs1, vs2, wo1, wo2, bo, out);
}

// round 17
// speedup vs baseline: 1.0774x; 1.0774x over previous
#include <cuda_runtime.h>
#include <cuda_bf16.h>
#include <math.h>
#include <stdint.h>

#define Bb 4
#define Ll 1024
#define Ee 1024
#define Hh 16
#define DHh 64
#define TOPKk 32

// -------- scratch (no allocs allowed) --------
__device__ float g_q [Bb*Ll*Ee];
__device__ float g_k [Bb*Ll*Ee];
__device__ float g_v [Bb*Ll*Ee];

// split planes
__device__ __nv_bfloat16 g_vs1[Bb*Ll*Ee];   // V split, then attn-out split
__device__ __nv_bfloat16 g_vs2[Bb*Ll*Ee];
__device__ __nv_bfloat16 g_wv1[Ee*Ee];
__device__ __nv_bfloat16 g_wv2[Ee*Ee];
__device__ __nv_bfloat16 g_wo1[Ee*Ee];
__device__ __nv_bfloat16 g_wo2[Ee*Ee];

// ============================================================
// Scalar fp32 GEMM — exact round-1 loads & fma chain
// (bit-identical); min-blocks bound forces 2 blocks/SM.
// ============================================================
#define GBM 128
#define GBN 128
#define GBK 16

__global__ __launch_bounds__(256, 2) void gemm_nt_bias(
    const float* __restrict__ X, const float* __restrict__ W,
    const float* __restrict__ bias, float* __restrict__ out,
    int M, int N, int K)
{
    __shared__ float As[GBK][GBM];
    __shared__ float Bs[GBK][GBN];

    const int tid = threadIdx.x;
    const int bm = blockIdx.y * GBM;
    const int bn = blockIdx.x * GBN;

    const int tr = (tid / 16) * 8;
    const int tc = (tid % 16) * 8;

    const int arow  = tid >> 2;
    const int acol4 = tid & 3;

    float acc[8][8] = {};

    for (int k0 = 0; k0 < K; k0 += GBK) {
        #pragma unroll
        for (int r = 0; r < 2; r++) {
            int row = arow + r * 64;
            float4 v = *(const float4*)(X + (size_t)(bm + row) * K + k0 + acol4 * 4);
            As[acol4*4+0][row] = v.x;
            As[acol4*4+1][row] = v.y;
            As[acol4*4+2][row] = v.z;
            As[acol4*4+3][row] = v.w;
        }
        #pragma unroll
        for (int r = 0; r < 2; r++) {
            int row = arow + r * 64;
            float4 v = *(const float4*)(W + (size_t)(bn + row) * K + k0 + acol4 * 4);
            Bs[acol4*4+0][row] = v.x;
            Bs[acol4*4+1][row] = v.y;
            Bs[acol4*4+2][row] = v.z;
            Bs[acol4*4+3][row] = v.w;
        }
        __syncthreads();

        #pragma unroll
        for (int k = 0; k < GBK; k++) {
            float ra[8], rb[8];
            #pragma unroll
            for (int i = 0; i < 8; i++) ra[i] = As[k][tr + i];
            #pragma unroll
            for (int j = 0; j < 8; j++) rb[j] = Bs[k][tc + j];
            #pragma unroll
            for (int i = 0; i < 8; i++)
                #pragma unroll
                for (int j = 0; j < 8; j++)
                    acc[i][j] = fmaf(ra[i], rb[j], acc[i][j]);
        }
        __syncthreads();
    }

    #pragma unroll
    for (int i = 0; i < 8; i++) {
        #pragma unroll
        for (int j = 0; j < 8; j++) {
            out[(size_t)(bm + tr + i) * N + bn + tc + j] = acc[i][j] + bias[bn + tc + j];
        }
    }
}

// ============================================================
// bf16x2 split
// ============================================================
__global__ void split2_kernel(const float* __restrict__ src,
                              __nv_bfloat16* __restrict__ p1,
                              __nv_bfloat16* __restrict__ p2, int n)
{
    int i = blockIdx.x * blockDim.x + threadIdx.x;
    if (i >= n) return;
    float x = src[i];
    __nv_bfloat16 b1 = __float2bfloat16_rn(x);
    float r1 = x - __bfloat162float(b1);
    p1[i] = b1;
    p2[i] = __float2bfloat16_rn(r1);
}

// ============================================================
// mma helpers
// ============================================================
__device__ __forceinline__ void mma16816(
    float& d0, float& d1, float& d2, float& d3,
    uint32_t a0, uint32_t a1, uint32_t a2, uint32_t a3,
    uint32_t b0, uint32_t b1)
{
    asm volatile(
        "mma.sync.aligned.m16n8k16.row.col.f32.bf16.bf16.f32 "
        "{%0,%1,%2,%3}, {%4,%5,%6,%7}, {%8,%9}, {%0,%1,%2,%3};"
        : "+f"(d0), "+f"(d1), "+f"(d2), "+f"(d3)
        : "r"(a0), "r"(a1), "r"(a2), "r"(a3), "r"(b0), "r"(b1));
}
__device__ __forceinline__ void ldsm_x4(uint32_t& r0, uint32_t& r1,
                                        uint32_t& r2, uint32_t& r3, uint32_t saddr)
{
    asm volatile("ldmatrix.sync.aligned.m8n8.x4.shared.b16 {%0,%1,%2,%3}, [%4];"
        : "=r"(r0), "=r"(r1), "=r"(r2), "=r"(r3) : "r"(saddr));
}
__device__ __forceinline__ uint32_t smem_u32(const void* p) {
    uint32_t a;
    asm("{ .reg .u64 t; cvta.to.shared.u64 t, %1; cvt.u32.u64 %0, t; }" : "=r"(a) : "l"(p));
    return a;
}
__device__ __forceinline__ void cp_async16(uint32_t saddr, const void* g) {
    asm volatile("cp.async.cg.shared.global [%0], [%1], 16;" :: "r"(saddr), "l"(g));
}
#define CP_COMMIT() asm volatile("cp.async.commit_group;" ::: "memory")
#define CP_WAIT(n)  asm volatile("cp.async.wait_group %0;" :: "n"(n) : "memory")

#define TK 1024
#define TN 1024
#define NCHUNK (TK / 32)
#define SROWB 80
#define TILE_B (128 * SROWB)
#define STAGE_B (4 * TILE_B)
#define TG_SMEM (2 * STAGE_B)

// ============================================================
// 3-term bf16x2 GEMM (v / out projections) — round-7 version
// ============================================================
__global__ __launch_bounds__(256, 2) void gemm_bf16x2_mma(
    const __nv_bfloat16* __restrict__ A1, const __nv_bfloat16* __restrict__ A2,
    const __nv_bfloat16* __restrict__ B1, const __nv_bfloat16* __restrict__ B2,
    const float* __restrict__ bias, float* __restrict__ out)
{
    extern __shared__ char smem[];
    const uint32_t smem_b = smem_u32(smem);

    const int tid = threadIdx.x;
    const int wid = tid >> 5;
    const int lane = tid & 31;
    const int g  = lane >> 2;
    const int tg = lane & 3;

    const int bm = blockIdx.y * 128;
    const int bn = blockIdx.x * 128;
    const int wm = (wid >> 1) * 32;
    const int wn = (wid & 1) * 64;

    const uint32_t lrow = (uint32_t)(lane & 15);
    const uint32_t lcol = (uint32_t)((lane >> 4) << 3);

    const __nv_bfloat16* gp[4] = {A1, A2, B1, B2};
    const int gbase[4] = {bm, bm, bn, bn};

    float acc[2][8][4] = {};

    for (int kc = 0; kc < NCHUNK + 1; kc++) {
        if (kc < NCHUNK) {
            const int k0 = kc * 32;
            const uint32_t stage_off = (uint32_t)(kc & 1) * STAGE_B;
            #pragma unroll
            for (int it = 0; it < 8; it++) {
                int c = tid + it * 256;
                int t = c >> 9;
                int rem = c & 511;
                int row = rem >> 2;
                int seg = rem & 3;
                uint32_t sa = smem_b + stage_off + (uint32_t)t * TILE_B
                            + (uint32_t)row * SROWB + (uint32_t)seg * 16;
                const __nv_bfloat16* gsrc = gp[t] + (size_t)(gbase[t] + row) * TK + k0 + seg * 8;
                cp_async16(sa, gsrc);
            }
            CP_COMMIT();
        }
        if (kc == 0) continue;

        if (kc < NCHUNK) { CP_WAIT(1); } else { CP_WAIT(0); }
        __syncthreads();

        const uint32_t st_u = smem_b + (uint32_t)((kc - 1) & 1) * STAGE_B;

        #pragma unroll
        for (int ks = 0; ks < 2; ks++) {
            const uint32_t coff = (uint32_t)(ks * 16) * 2 + lcol * 2;

            uint32_t af[2][2][4];
            #pragma unroll
            for (int p = 0; p < 2; p++)
                #pragma unroll
                for (int mt = 0; mt < 2; mt++) {
                    uint32_t addr = st_u + (uint32_t)p * TILE_B
                                  + ((uint32_t)(wm + mt * 16) + lrow) * SROWB + coff;
                    ldsm_x4(af[p][mt][0], af[p][mt][1], af[p][mt][2], af[p][mt][3], addr);
                }
            #pragma unroll
            for (int np = 0; np < 4; np++) {
                uint32_t bf[2][2][2];
                #pragma unroll
                for (int p = 0; p < 2; p++) {
                    uint32_t addr = st_u + (uint32_t)(2 + p) * TILE_B
                                  + ((uint32_t)(wn + np * 16) + lrow) * SROWB + coff;
                    ldsm_x4(bf[p][0][0], bf[p][1][0], bf[p][0][1], bf[p][1][1], addr);
                }
                #pragma unroll
                for (int ntl = 0; ntl < 2; ntl++) {
                    const int nt = np * 2 + ntl;
                    #pragma unroll
                    for (int mt = 0; mt < 2; mt++) {
                        mma16816(acc[mt][nt][0], acc[mt][nt][1], acc[mt][nt][2], acc[mt][nt][3],
                                 af[0][mt][0], af[0][mt][1], af[0][mt][2], af[0][mt][3],
                                 bf[0][ntl][0], bf[0][ntl][1]);
                        mma16816(acc[mt][nt][0], acc[mt][nt][1], acc[mt][nt][2], acc[mt][nt][3],
                                 af[0][mt][0], af[0][mt][1], af[0][mt][2], af[0][mt][3],
                                 bf[1][ntl][0], bf[1][ntl][1]);
                        mma16816(acc[mt][nt][0], acc[mt][nt][1], acc[mt][nt][2], acc[mt][nt][3],
                                 af[1][mt][0], af[1][mt][1], af[1][mt][2], af[1][mt][3],
                                 bf[0][ntl][0], bf[0][ntl][1]);
                    }
                }
            }
        }
        __syncthreads();
    }

    #pragma unroll
    for (int mt = 0; mt < 2; mt++) {
        #pragma unroll
        for (int nt = 0; nt < 8; nt++) {
            int m0 = bm + wm + mt * 16 + g;
            int n0 = bn + wn + nt * 8 + tg * 2;
            float b0 = bias[n0], b1 = bias[n0 + 1];
            float2 lo = make_float2(acc[mt][nt][0] + b0, acc[mt][nt][1] + b1);
            float2 hi = make_float2(acc[mt][nt][2] + b0, acc[mt][nt][3] + b1);
            *(float2*)(out + (size_t)m0 * TN + n0)       = lo;
            *(float2*)(out + (size_t)(m0 + 8) * TN + n0) = hi;
        }
    }
}

// ============================================================
// Attention (round-14 version — bitmask deferred-insert scan,
// fused bf16x2 split epilogue; bit-identical selection)
// ============================================================
#define ATT_QT 128
#define ATT_KT 32
#define ATT_THREADS 256

#define SM_QT   0
#define SM_KT   (SM_QT + 64*128)
#define SM_S    (SM_KT + 64*ATT_KT)
#define SM_TV   (SM_S  + 128*33)
#define SM_TI   (SM_TV + 128*33)
#define ATT_SMEM_FLOATS (SM_TI + 128*33)

__global__ __launch_bounds__(ATT_THREADS) void attn_topk_kernel(
    const float* __restrict__ gq, const float* __restrict__ gk,
    const float* __restrict__ gv,
    __nv_bfloat16* __restrict__ ao1, __nv_bfloat16* __restrict__ ao2)
{
    extern __shared__ float sm[];
    float* sQt = sm + SM_QT;
    float* sKt = sm + SM_KT;
    float* sS  = sm + SM_S;
    float* sTV = sm + SM_TV;
    int*   sTI = (int*)(sm + SM_TI);

    const int tid = threadIdx.x;
    const int bh  = blockIdx.y;
    const int b   = bh / Hh;
    const int h   = bh % Hh;
    const int l0  = blockIdx.x * ATT_QT;

    for (int idx = tid; idx < ATT_QT * DHh; idx += ATT_THREADS) {
        int qq = idx >> 6;
        int d  = idx & 63;
        sQt[d * ATT_QT + qq] = gq[((size_t)(b * Ll + l0 + qq)) * Ee + h * DHh + d];
    }

    if (tid < 128) {
        #pragma unroll
        for (int j = 0; j < TOPKk; j++) {
            sTV[tid * 33 + j] = -INFINITY;
            sTI[tid * 33 + j] = 0;
        }
    }
    float curMin = -INFINITY;
    int   curPos = 0;

    const int ty = tid >> 3;
    const int tx = tid & 7;

    for (int kt = 0; kt < Ll / ATT_KT; kt++) {
        for (int idx = tid; idx < ATT_KT * DHh; idx += ATT_THREADS) {
            int kk = idx >> 6;
            int d  = idx & 63;
            sKt[d * ATT_KT + kk] = gk[((size_t)(b * Ll + kt * ATT_KT + kk)) * Ee + h * DHh + d];
        }
        __syncthreads();

        float acc[4][4] = {};
        #pragma unroll 8
        for (int d = 0; d < DHh; d++) {
            float ra[4], rb[4];
            *(float4*)&ra[0] = *(const float4*)&sQt[d * ATT_QT + ty * 4];
            *(float4*)&rb[0] = *(const float4*)&sKt[d * ATT_KT + tx * 4];
            #pragma unroll
            for (int i = 0; i < 4; i++)
                #pragma unroll
                for (int j = 0; j < 4; j++)
                    acc[i][j] = fmaf(ra[i], rb[j], acc[i][j]);
        }
        #pragma unroll
        for (int i = 0; i < 4; i++)
            #pragma unroll
            for (int j = 0; j < 4; j++)
                sS[(ty * 4 + i) * 33 + tx * 4 + j] = acc[i][j] * 0.125f;
        __syncthreads();

        if (tid < 128) {
            unsigned int mask = 0;
            const float gateMin = curMin;
            #pragma unroll
            for (int kk = 0; kk < ATT_KT; kk++) {
                float s = sS[tid * 33 + kk];
                if (s > gateMin) mask |= (1u << kk);
            }
            while (mask) {
                const int kk = __ffs(mask) - 1;
                mask &= mask - 1;
                float s = sS[tid * 33 + kk];
                if (s > curMin) {
                    sTV[tid * 33 + curPos] = s;
                    sTI[tid * 33 + curPos] = kt * ATT_KT + kk;
                    float mn = sTV[tid * 33];
                    int   mp = 0;
                    #pragma unroll
                    for (int j = 1; j < TOPKk; j++) {
                        float v = sTV[tid * 33 + j];
                        if (v < mn) { mn = v; mp = j; }
                    }
                    curMin = mn; curPos = mp;
                }
            }
        }
        __syncthreads();
    }

    const int warp = tid >> 5;
    const int lane = tid & 31;
    for (int qi = warp; qi < ATT_QT; qi += 8) {
        float v  = sTV[qi * 33 + lane];
        int   ki = sTI[qi * 33 + lane];

        float mx = v;
        #pragma unroll
        for (int o = 16; o; o >>= 1) mx = fmaxf(mx, __shfl_xor_sync(0xffffffffu, mx, o));
        float e = expf(v - mx);
        float se = e;
        #pragma unroll
        for (int o = 16; o; o >>= 1) se += __shfl_xor_sync(0xffffffffu, se, o);
        float w = e / se;

        float a0 = 0.f, a1 = 0.f;
        #pragma unroll
        for (int j = 0; j < TOPKk; j++) {
            float wj = __shfl_sync(0xffffffffu, w, j);
            int   kj = __shfl_sync(0xffffffffu, ki, j);
            const float* vr = gv + ((size_t)(b * Ll + kj)) * Ee + h * DHh;
            a0 = fmaf(wj, vr[lane],      a0);
            a1 = fmaf(wj, vr[lane + 32], a1);
        }
        size_t base = ((size_t)(b * Ll + l0 + qi)) * Ee + h * DHh;
        __nv_bfloat16 b0 = __float2bfloat16_rn(a0);
        ao1[base + lane]      = b0;
        ao2[base + lane]      = __float2bfloat16_rn(a0 - __bfloat162float(b0));
        __nv_bfloat16 b1h = __float2bfloat16_rn(a1);
        ao1[base + lane + 32] = b1h;
        ao2[base + lane + 32] = __float2bfloat16_rn(a1 - __bfloat162float(b1h));
    }
}

// ============================================================
extern "C" void kernel_launch(void* const* d_in, const int* in_sizes, int n_in,
                              void* d_out, int out_size)
{
    const float* Q  = (const float*)d_in[0];
    const float* K_ = (const float*)d_in[1];
    const float* V  = (const float*)d_in[2];
    const float* Wq = (const float*)d_in[3];
    const float* bq = (const float*)d_in[4];
    const float* Wk = (const float*)d_in[5];
    const float* bk = (const float*)d_in[6];
    const float* Wv = (const float*)d_in[7];
    const float* bv = (const float*)d_in[8];
    const float* Wo = (const float*)d_in[9];
    const float* bo = (const float*)d_in[10];
    float* out = (float*)d_out;

    float *gq, *gk, *gv;
    cudaGetSymbolAddress((void**)&gq,  g_q);
    cudaGetSymbolAddress((void**)&gk,  g_k);
    cudaGetSymbolAddress((void**)&gv,  g_v);
    __nv_bfloat16 *vs1, *vs2, *wv1, *wv2, *wo1, *wo2;
    cudaGetSymbolAddress((void**)&vs1, g_vs1);
    cudaGetSymbolAddress((void**)&vs2, g_vs2);
    cudaGetSymbolAddress((void**)&wv1, g_wv1);
    cudaGetSymbolAddress((void**)&wv2, g_wv2);
    cudaGetSymbolAddress((void**)&wo1, g_wo1);
    cudaGetSymbolAddress((void**)&wo2, g_wo2);

    static cudaStream_t sV = nullptr;
    static cudaEvent_t eFork = nullptr, eV = nullptr;
    if (sV == nullptr) {
        cudaStreamCreateWithFlags(&sV, cudaStreamNonBlocking);
        cudaEventCreateWithFlags(&eFork, cudaEventDisableTiming);
        cudaEventCreateWithFlags(&eV, cudaEventDisableTiming);
    }

    const int M = Bb * Ll;
    const int N = Ee;
    const int K = Ee;

    dim3 gblock(256);
    dim3 ggrid(N / GBN, M / GBM);
    dim3 tgrid(N / 128, M / 128);

    cudaFuncSetAttribute(gemm_bf16x2_mma,
                         cudaFuncAttributeMaxDynamicSharedMemorySize, TG_SMEM);
    size_t attSmem = ATT_SMEM_FLOATS * sizeof(float);
    cudaFuncSetAttribute(attn_topk_kernel,
                         cudaFuncAttributeMaxDynamicSharedMemorySize, (int)attSmem);

    // ---- fork: v-path runs concurrently with q/k scalar GEMMs ----
    cudaEventRecord(eFork, 0);
    cudaStreamWaitEvent(sV, eFork, 0);

    split2_kernel<<<(M*K + 255)/256, 256, 0, sV>>>(V,  vs1, vs2, M*K);
    split2_kernel<<<(N*K + 255)/256, 256, 0, sV>>>(Wv, wv1, wv2, N*K);
    gemm_bf16x2_mma<<<tgrid, 256, TG_SMEM, sV>>>(vs1, vs2, wv1, wv2, bv, gv);
    split2_kernel<<<(N*K + 255)/256, 256, 0, sV>>>(Wo, wo1, wo2, N*K);
    cudaEventRecord(eV, sV);

    // ---- main: q, k projections (scalar fp32, bit-identical) ----
    gemm_nt_bias<<<ggrid, gblock>>>(Q,  Wq, bq, gq, M, N, K);
    gemm_nt_bias<<<ggrid, gblock>>>(K_, Wk, bk, gk, M, N, K);

    // ---- join: attention needs q, k (main) and v (side) ----
    cudaStreamWaitEvent(0, eV, 0);

    dim3 agrid(Ll / ATT_QT, Bb * Hh);
    attn_topk_kernel<<<agrid, ATT_THREADS, attSmem>>>(gq, gk, gv, vs1, vs2);

    // ---- output projection (3-term bf16x2), split fused into attn ----
    gemm_bf16x2_mma<<<tgrid, 256, TG_SMEM>>>(vs1, vs2, wo1, wo2, bo, out);
}